// round 1
// baseline (speedup 1.0000x reference)
#include <cuda_runtime.h>
#include <math.h>
#include <stdint.h>

// Problem constants
#define Bn   16384
#define Sn   256
#define En   128
#define Hn   128
#define Nt   34
#define TEMP 0.1f
#define EPSn 1e-8f

// Tiling
#define TB      64      // batch rows per block
#define THREADS 256
#define KT      16      // k-tile depth

// SMEM strides (padded to dodge bank conflicts, keep 16B alignment)
#define ST_STRIDE   260
#define H_STRIDE    132
#define LANG_STRIDE 132

// Output section offsets (flat concat: rep_vec, log_task_prob, latent_target, latent_vec)
#define OFF_REP  0
#define OFF_LOGP ((size_t)Bn * (Sn + En))
#define OFF_LT   (OFF_LOGP + (size_t)Bn * Nt)
#define OFF_LV   (OFF_LT + (size_t)Bn * En)

__global__ __launch_bounds__(THREADS, 1)
void slp_encoder_fused(const float* __restrict__ state,
                       const int*   __restrict__ task_id,
                       const float* __restrict__ prior,
                       const float* __restrict__ W1, const float* __restrict__ b1,
                       const float* __restrict__ W2, const float* __restrict__ b2,
                       const float* __restrict__ W3, const float* __restrict__ b3,
                       const float* __restrict__ lang_emb,
                       float* __restrict__ out)
{
    extern __shared__ float sm[];
    float* sState = sm;                              // TB*ST_STRIDE
    float* sH     = sState + TB * ST_STRIDE;         // TB*H_STRIDE
    float* sW     = sH + TB * H_STRIDE;              // KT*Hn
    float* sLang  = sW + KT * Hn;                    // Nt*LANG_STRIDE
    float* sP     = sLang + Nt * LANG_STRIDE;        // TB*Nt
    float* sCos   = sP + TB * Nt;                    // TB*Nt
    int*   sTid   = (int*)(sCos + TB * Nt);          // TB

    const int tid = threadIdx.x;
    const int tx  = tid & 15;       // 0..15 -> output column group (8 cols)
    const int ty  = tid >> 4;       // 0..15 -> output row group (4 rows)
    const int row0 = blockIdx.x * TB;

    // ---------------- Prolog ----------------
    // Load state tile [TB,256] into SMEM (float4)
    {
        const float4* g = (const float4*)(state + (size_t)row0 * Sn);
        int c4 = tid & 63;          // float4 col 0..63
        int r  = tid >> 6;          // 0..3
        #pragma unroll
        for (int rr = r; rr < TB; rr += 4) {
            float4 v = g[rr * (Sn / 4) + c4];
            *(float4*)(sState + rr * ST_STRIDE + c4 * 4) = v;
        }
    }
    // task ids + prior softmax (one thread per row)
    if (tid < TB) {
        sTid[tid] = task_id[row0 + tid];
        const float* pr = prior + (size_t)(row0 + tid) * Nt;
        float m = -1e30f;
        #pragma unroll
        for (int n = 0; n < Nt; ++n) m = fmaxf(m, pr[n]);
        float s = 0.f;
        #pragma unroll
        for (int n = 0; n < Nt; ++n) { float e = expf(pr[n] - m); sP[tid * Nt + n] = e; s += e; }
        float inv = 1.f / s;
        #pragma unroll
        for (int n = 0; n < Nt; ++n) sP[tid * Nt + n] *= inv;
    }
    // normalized lang table (one warp per row, 8 warps)
    {
        int warp = tid >> 5, lane = tid & 31;
        for (int n = warp; n < Nt; n += 8) {
            float4 v = ((const float4*)(lang_emb + (size_t)n * En))[lane];
            float ss = v.x * v.x + v.y * v.y + v.z * v.z + v.w * v.w;
            #pragma unroll
            for (int o = 16; o > 0; o >>= 1) ss += __shfl_xor_sync(0xffffffffu, ss, o);
            float nm  = sqrtf(ss);
            float inv = 1.f / fmaxf(nm, EPSn);
            float4 w = make_float4(v.x * inv, v.y * inv, v.z * inv, v.w * inv);
            *(float4*)(sLang + n * LANG_STRIDE + lane * 4) = w;
        }
    }
    __syncthreads();

    // latent_vec accumulator in registers
    float lat[4][8];
    #pragma unroll
    for (int i = 0; i < 4; ++i)
        #pragma unroll
        for (int j = 0; j < 8; ++j) lat[i][j] = 0.f;

    // ---------------- Per-task loop ----------------
    for (int n = 0; n < Nt; ++n) {
        float c[4][8];

        // ===== GEMM1: [TB,256] x W1[n][256,128] -> relu -> sH =====
        #pragma unroll
        for (int i = 0; i < 4; ++i)
            #pragma unroll
            for (int j = 0; j < 8; ++j) c[i][j] = 0.f;

        {
            const float* Wn = W1 + (size_t)n * Sn * Hn;
            for (int kt = 0; kt < Sn / KT; ++kt) {
                const float4* g = (const float4*)(Wn + kt * KT * Hn);
                ((float4*)sW)[tid]       = g[tid];
                ((float4*)sW)[tid + 256] = g[tid + 256];
                __syncthreads();
                #pragma unroll
                for (int k = 0; k < KT; ++k) {
                    float a[4];
                    #pragma unroll
                    for (int i = 0; i < 4; ++i)
                        a[i] = sState[(ty * 4 + i) * ST_STRIDE + kt * KT + k];
                    float4 bv0 = *(const float4*)(sW + k * Hn + tx * 8);
                    float4 bv1 = *(const float4*)(sW + k * Hn + tx * 8 + 4);
                    float bf[8] = {bv0.x, bv0.y, bv0.z, bv0.w, bv1.x, bv1.y, bv1.z, bv1.w};
                    #pragma unroll
                    for (int i = 0; i < 4; ++i)
                        #pragma unroll
                        for (int j = 0; j < 8; ++j) c[i][j] = fmaf(a[i], bf[j], c[i][j]);
                }
                __syncthreads();
            }
        }
        {
            float4 bb0 = *(const float4*)(b1 + (size_t)n * Hn + tx * 8);
            float4 bb1 = *(const float4*)(b1 + (size_t)n * Hn + tx * 8 + 4);
            float bb[8] = {bb0.x, bb0.y, bb0.z, bb0.w, bb1.x, bb1.y, bb1.z, bb1.w};
            #pragma unroll
            for (int i = 0; i < 4; ++i) {
                float4 v0, v1;
                v0.x = fmaxf(c[i][0] + bb[0], 0.f); v0.y = fmaxf(c[i][1] + bb[1], 0.f);
                v0.z = fmaxf(c[i][2] + bb[2], 0.f); v0.w = fmaxf(c[i][3] + bb[3], 0.f);
                v1.x = fmaxf(c[i][4] + bb[4], 0.f); v1.y = fmaxf(c[i][5] + bb[5], 0.f);
                v1.z = fmaxf(c[i][6] + bb[6], 0.f); v1.w = fmaxf(c[i][7] + bb[7], 0.f);
                *(float4*)(sH + (ty * 4 + i) * H_STRIDE + tx * 8)     = v0;
                *(float4*)(sH + (ty * 4 + i) * H_STRIDE + tx * 8 + 4) = v1;
            }
        }
        __syncthreads();

        // ===== GEMM2: sH x W2[n][128,128] -> relu -> sH =====
        #pragma unroll
        for (int i = 0; i < 4; ++i)
            #pragma unroll
            for (int j = 0; j < 8; ++j) c[i][j] = 0.f;
        {
            const float* Wn = W2 + (size_t)n * Hn * Hn;
            for (int kt = 0; kt < Hn / KT; ++kt) {
                const float4* g = (const float4*)(Wn + kt * KT * Hn);
                ((float4*)sW)[tid]       = g[tid];
                ((float4*)sW)[tid + 256] = g[tid + 256];
                __syncthreads();
                #pragma unroll
                for (int k = 0; k < KT; ++k) {
                    float a[4];
                    #pragma unroll
                    for (int i = 0; i < 4; ++i)
                        a[i] = sH[(ty * 4 + i) * H_STRIDE + kt * KT + k];
                    float4 bv0 = *(const float4*)(sW + k * Hn + tx * 8);
                    float4 bv1 = *(const float4*)(sW + k * Hn + tx * 8 + 4);
                    float bf[8] = {bv0.x, bv0.y, bv0.z, bv0.w, bv1.x, bv1.y, bv1.z, bv1.w};
                    #pragma unroll
                    for (int i = 0; i < 4; ++i)
                        #pragma unroll
                        for (int j = 0; j < 8; ++j) c[i][j] = fmaf(a[i], bf[j], c[i][j]);
                }
                __syncthreads();
            }
        }
        {
            float4 bb0 = *(const float4*)(b2 + (size_t)n * Hn + tx * 8);
            float4 bb1 = *(const float4*)(b2 + (size_t)n * Hn + tx * 8 + 4);
            float bb[8] = {bb0.x, bb0.y, bb0.z, bb0.w, bb1.x, bb1.y, bb1.z, bb1.w};
            // all reads of sH finished at the loop-final __syncthreads -> safe to overwrite
            #pragma unroll
            for (int i = 0; i < 4; ++i) {
                float4 v0, v1;
                v0.x = fmaxf(c[i][0] + bb[0], 0.f); v0.y = fmaxf(c[i][1] + bb[1], 0.f);
                v0.z = fmaxf(c[i][2] + bb[2], 0.f); v0.w = fmaxf(c[i][3] + bb[3], 0.f);
                v1.x = fmaxf(c[i][4] + bb[4], 0.f); v1.y = fmaxf(c[i][5] + bb[5], 0.f);
                v1.z = fmaxf(c[i][6] + bb[6], 0.f); v1.w = fmaxf(c[i][7] + bb[7], 0.f);
                *(float4*)(sH + (ty * 4 + i) * H_STRIDE + tx * 8)     = v0;
                *(float4*)(sH + (ty * 4 + i) * H_STRIDE + tx * 8 + 4) = v1;
            }
        }
        __syncthreads();

        // ===== GEMM3: sH x W3[n][128,128] -> q =====
        #pragma unroll
        for (int i = 0; i < 4; ++i)
            #pragma unroll
            for (int j = 0; j < 8; ++j) c[i][j] = 0.f;
        {
            const float* Wn = W3 + (size_t)n * Hn * En;
            for (int kt = 0; kt < Hn / KT; ++kt) {
                const float4* g = (const float4*)(Wn + kt * KT * En);
                ((float4*)sW)[tid]       = g[tid];
                ((float4*)sW)[tid + 256] = g[tid + 256];
                __syncthreads();
                #pragma unroll
                for (int k = 0; k < KT; ++k) {
                    float a[4];
                    #pragma unroll
                    for (int i = 0; i < 4; ++i)
                        a[i] = sH[(ty * 4 + i) * H_STRIDE + kt * KT + k];
                    float4 bv0 = *(const float4*)(sW + k * En + tx * 8);
                    float4 bv1 = *(const float4*)(sW + k * En + tx * 8 + 4);
                    float bf[8] = {bv0.x, bv0.y, bv0.z, bv0.w, bv1.x, bv1.y, bv1.z, bv1.w};
                    #pragma unroll
                    for (int i = 0; i < 4; ++i)
                        #pragma unroll
                        for (int j = 0; j < 8; ++j) c[i][j] = fmaf(a[i], bf[j], c[i][j]);
                }
                __syncthreads();
            }
        }

        // ===== Epilogue for task n =====
        {
            float4 bb0 = *(const float4*)(b3 + (size_t)n * En + tx * 8);
            float4 bb1 = *(const float4*)(b3 + (size_t)n * En + tx * 8 + 4);
            float bb[8] = {bb0.x, bb0.y, bb0.z, bb0.w, bb1.x, bb1.y, bb1.z, bb1.w};
            #pragma unroll
            for (int i = 0; i < 4; ++i) {
                #pragma unroll
                for (int j = 0; j < 8; ++j) c[i][j] += bb[j];

                // row sum-of-squares across the 16-lane row group
                float ss = 0.f;
                #pragma unroll
                for (int j = 0; j < 8; ++j) ss += c[i][j] * c[i][j];
                #pragma unroll
                for (int o = 1; o < 16; o <<= 1) ss += __shfl_xor_sync(0xffffffffu, ss, o);
                float inv = rsqrtf(ss);

                int rloc = ty * 4 + i;
                int tsk  = sTid[rloc];

                float qh[8];
                float dot = 0.f;
                #pragma unroll
                for (int j = 0; j < 8; ++j) {
                    qh[j] = c[i][j] * inv;
                    dot += qh[j] * sLang[tsk * LANG_STRIDE + tx * 8 + j];
                }
                #pragma unroll
                for (int o = 1; o < 16; o <<= 1) dot += __shfl_xor_sync(0xffffffffu, dot, o);
                if (tx == 0) sCos[rloc * Nt + n] = dot;

                float p = sP[rloc * Nt + n];
                #pragma unroll
                for (int j = 0; j < 8; ++j) lat[i][j] = fmaf(qh[j], p, lat[i][j]);

                if (tsk == n) {
                    size_t base = OFF_LT + (size_t)(row0 + rloc) * En + tx * 8;
                    *(float4*)(out + base)     = make_float4(qh[0], qh[1], qh[2], qh[3]);
                    *(float4*)(out + base + 4) = make_float4(qh[4], qh[5], qh[6], qh[7]);
                }
            }
        }
        __syncthreads();   // sCos complete & sH free before next n
    }

    // ---------------- Final outputs ----------------
    // log_softmax of cos/TEMP per row
    if (tid < TB) {
        float m = -1e30f;
        #pragma unroll
        for (int n = 0; n < Nt; ++n) m = fmaxf(m, sCos[tid * Nt + n] * (1.0f / TEMP));
        float s = 0.f;
        #pragma unroll
        for (int n = 0; n < Nt; ++n) s += expf(sCos[tid * Nt + n] * (1.0f / TEMP) - m);
        float lse = m + logf(s);
        float* o = out + OFF_LOGP + (size_t)(row0 + tid) * Nt;
        #pragma unroll
        for (int n = 0; n < Nt; ++n) o[n] = sCos[tid * Nt + n] * (1.0f / TEMP) - lse;
    }

    // latent_vec -> rep_vec[:,256:384] and latent_vec section
    #pragma unroll
    for (int i = 0; i < 4; ++i) {
        int r = row0 + ty * 4 + i;
        float4 v0 = make_float4(lat[i][0], lat[i][1], lat[i][2], lat[i][3]);
        float4 v1 = make_float4(lat[i][4], lat[i][5], lat[i][6], lat[i][7]);
        *(float4*)(out + (size_t)r * (Sn + En) + Sn + tx * 8)     = v0;
        *(float4*)(out + (size_t)r * (Sn + En) + Sn + tx * 8 + 4) = v1;
        *(float4*)(out + OFF_LV + (size_t)r * En + tx * 8)        = v0;
        *(float4*)(out + OFF_LV + (size_t)r * En + tx * 8 + 4)    = v1;
    }

    // rep_vec[:,0:256] = state (from SMEM tile)
    {
        int c4 = tid & 63;
        int r  = tid >> 6;
        #pragma unroll
        for (int rr = r; rr < TB; rr += 4) {
            float4 v = *(const float4*)(sState + rr * ST_STRIDE + c4 * 4);
            *(float4*)(out + (size_t)(row0 + rr) * (Sn + En) + c4 * 4) = v;
        }
    }
}

extern "C" void kernel_launch(void* const* d_in, const int* in_sizes, int n_in,
                              void* d_out, int out_size) {
    const float* state    = (const float*)d_in[0];
    const int*   task_id  = (const int*)  d_in[1];
    const float* prior    = (const float*)d_in[2];
    const float* W1       = (const float*)d_in[3];
    const float* b1       = (const float*)d_in[4];
    const float* W2       = (const float*)d_in[5];
    const float* b2       = (const float*)d_in[6];
    const float* W3       = (const float*)d_in[7];
    const float* b3       = (const float*)d_in[8];
    const float* lang_emb = (const float*)d_in[9];
    float* out = (float*)d_out;

    size_t smem = (size_t)(TB * ST_STRIDE + TB * H_STRIDE + KT * Hn +
                           Nt * LANG_STRIDE + TB * Nt * 2) * sizeof(float) +
                  TB * sizeof(int);

    static bool attr_set = false;
    if (!attr_set) {
        cudaFuncSetAttribute(slp_encoder_fused,
                             cudaFuncAttributeMaxDynamicSharedMemorySize,
                             (int)(192 * 1024));
        attr_set = true;
    }

    slp_encoder_fused<<<Bn / TB, THREADS, smem>>>(
        state, task_id, prior, W1, b1, W2, b2, W3, b3, lang_emb, out);
}

// round 2
// speedup vs baseline: 1.7012x; 1.7012x over previous
#include <cuda_runtime.h>
#include <math.h>
#include <stdint.h>

// Problem constants
#define Bn   16384
#define Sn   256
#define En   128
#define Hn   128
#define Nt   34
#define TEMP 0.1f
#define EPSn 1e-8f

// Tiling
#define TB      64
#define THREADS 256

#define A_STRIDE 20     // 64x16 A slice rows padded to 20 floats (16B-aligned, conflict-free)
#define H_STRIDE 132

// Output section offsets (flat concat: rep_vec, log_task_prob, latent_target, latent_vec)
#define OFF_LOGP ((size_t)Bn * (Sn + En))
#define OFF_LT   (OFF_LOGP + (size_t)Bn * Nt)
#define OFF_LV   (OFF_LT + (size_t)Bn * En)

// smem float offsets
#define SA_OFF   0
#define SW_OFF   (SA_OFF + 2 * 64 * A_STRIDE)        // 2560
#define SH_OFF   (SW_OFF + 2 * 16 * 128)             // 6656
#define SL_OFF   (SH_OFF + 64 * H_STRIDE)            // 15104
#define SP_OFF   (SL_OFF + Nt * 128)                 // 19456
#define SC_OFF   (SP_OFF + TB * Nt)                  // 21632
#define STID_OFF (SC_OFF + TB * Nt)                  // 23808
#define SMEM_WORDS (STID_OFF + TB)                   // 23872

__device__ __forceinline__ void cp16(uint32_t dst, const float* src) {
    asm volatile("cp.async.ca.shared.global [%0], [%1], 16;" :: "r"(dst), "l"(src));
}
__device__ __forceinline__ void cp_commit() { asm volatile("cp.async.commit_group;"); }
__device__ __forceinline__ void cp_wait0()  { asm volatile("cp.async.wait_group 0;"); }

__global__ __launch_bounds__(THREADS, 2)
void slp_encoder_fused(const float* __restrict__ state,
                       const int*   __restrict__ task_id,
                       const float* __restrict__ prior,
                       const float* __restrict__ W1, const float* __restrict__ b1,
                       const float* __restrict__ W2, const float* __restrict__ b2,
                       const float* __restrict__ W3, const float* __restrict__ b3,
                       const float* __restrict__ lang_emb,
                       float* __restrict__ out)
{
    extern __shared__ float sm[];
    float* sA    = sm + SA_OFF;    // 2 x 64 x A_STRIDE
    float* sW    = sm + SW_OFF;    // 2 x 16 x 128
    float* sH    = sm + SH_OFF;    // 64 x H_STRIDE
    float* sLang = sm + SL_OFF;    // Nt x 128
    float* sP    = sm + SP_OFF;    // TB x Nt
    float* sCos  = sm + SC_OFF;    // TB x Nt
    int*   sTid  = (int*)(sm + STID_OFF);

    const int tid  = threadIdx.x;
    const int tx   = tid & 15;
    const int ty   = tid >> 4;
    const int tx4  = tx * 4;
    const int row0 = blockIdx.x * TB;

    const uint32_t sA_u = (uint32_t)__cvta_generic_to_shared(sA);
    const uint32_t sW_u = (uint32_t)__cvta_generic_to_shared(sW);

    // ---------------- Prolog ----------------
    if (tid < TB) {
        sTid[tid] = task_id[row0 + tid];
        const float* pr = prior + (size_t)(row0 + tid) * Nt;
        float m = -1e30f;
        #pragma unroll
        for (int n = 0; n < Nt; ++n) m = fmaxf(m, pr[n]);
        float s = 0.f;
        #pragma unroll
        for (int n = 0; n < Nt; ++n) { float e = expf(pr[n] - m); sP[tid * Nt + n] = e; s += e; }
        float inv = 1.f / s;
        #pragma unroll
        for (int n = 0; n < Nt; ++n) sP[tid * Nt + n] *= inv;
    }
    {   // normalized lang table
        int warp = tid >> 5, lane = tid & 31;
        for (int n = warp; n < Nt; n += 8) {
            float4 v = ((const float4*)(lang_emb + (size_t)n * En))[lane];
            float ss = v.x * v.x + v.y * v.y + v.z * v.z + v.w * v.w;
            #pragma unroll
            for (int o = 16; o > 0; o >>= 1) ss += __shfl_xor_sync(0xffffffffu, ss, o);
            float inv = 1.f / fmaxf(sqrtf(ss), EPSn);
            *(float4*)(sLang + n * 128 + lane * 4) =
                make_float4(v.x * inv, v.y * inv, v.z * inv, v.w * inv);
        }
    }
    __syncthreads();

    float lat[4][8];
    #pragma unroll
    for (int i = 0; i < 4; ++i)
        #pragma unroll
        for (int j = 0; j < 8; ++j) lat[i][j] = 0.f;

    const int ar = tid >> 2;        // A-slice row this thread copies
    const int ac = (tid & 3) * 4;   // A-slice col (floats)

    // inner-product step macro: 32 FMAs
    #define KSTEP(APTR, ASTR, KCOL, BW)                                          \
    {                                                                            \
        float a0 = (APTR)[(ty * 4 + 0) * (ASTR) + (KCOL)];                       \
        float a1 = (APTR)[(ty * 4 + 1) * (ASTR) + (KCOL)];                       \
        float a2 = (APTR)[(ty * 4 + 2) * (ASTR) + (KCOL)];                       \
        float a3 = (APTR)[(ty * 4 + 3) * (ASTR) + (KCOL)];                       \
        float4 bv0 = *(const float4*)((BW) + tx4);                               \
        float4 bv1 = *(const float4*)((BW) + 64 + tx4);                          \
        c[0][0]=fmaf(a0,bv0.x,c[0][0]); c[0][1]=fmaf(a0,bv0.y,c[0][1]);          \
        c[0][2]=fmaf(a0,bv0.z,c[0][2]); c[0][3]=fmaf(a0,bv0.w,c[0][3]);          \
        c[0][4]=fmaf(a0,bv1.x,c[0][4]); c[0][5]=fmaf(a0,bv1.y,c[0][5]);          \
        c[0][6]=fmaf(a0,bv1.z,c[0][6]); c[0][7]=fmaf(a0,bv1.w,c[0][7]);          \
        c[1][0]=fmaf(a1,bv0.x,c[1][0]); c[1][1]=fmaf(a1,bv0.y,c[1][1]);          \
        c[1][2]=fmaf(a1,bv0.z,c[1][2]); c[1][3]=fmaf(a1,bv0.w,c[1][3]);          \
        c[1][4]=fmaf(a1,bv1.x,c[1][4]); c[1][5]=fmaf(a1,bv1.y,c[1][5]);          \
        c[1][6]=fmaf(a1,bv1.z,c[1][6]); c[1][7]=fmaf(a1,bv1.w,c[1][7]);          \
        c[2][0]=fmaf(a2,bv0.x,c[2][0]); c[2][1]=fmaf(a2,bv0.y,c[2][1]);          \
        c[2][2]=fmaf(a2,bv0.z,c[2][2]); c[2][3]=fmaf(a2,bv0.w,c[2][3]);          \
        c[2][4]=fmaf(a2,bv1.x,c[2][4]); c[2][5]=fmaf(a2,bv1.y,c[2][5]);          \
        c[2][6]=fmaf(a2,bv1.z,c[2][6]); c[2][7]=fmaf(a2,bv1.w,c[2][7]);          \
        c[3][0]=fmaf(a3,bv0.x,c[3][0]); c[3][1]=fmaf(a3,bv0.y,c[3][1]);          \
        c[3][2]=fmaf(a3,bv0.z,c[3][2]); c[3][3]=fmaf(a3,bv0.w,c[3][3]);          \
        c[3][4]=fmaf(a3,bv1.x,c[3][4]); c[3][5]=fmaf(a3,bv1.y,c[3][5]);          \
        c[3][6]=fmaf(a3,bv1.z,c[3][6]); c[3][7]=fmaf(a3,bv1.w,c[3][7]);          \
    }

    #define RELU_STORE_H(BIAS)                                                   \
    {                                                                            \
        const float* bv = (BIAS);                                                \
        float4 bb0 = *(const float4*)(bv + tx4);                                 \
        float4 bb1 = *(const float4*)(bv + 64 + tx4);                            \
        _Pragma("unroll")                                                        \
        for (int i = 0; i < 4; ++i) {                                            \
            float4 v0, v1;                                                       \
            v0.x = fmaxf(c[i][0] + bb0.x, 0.f); v0.y = fmaxf(c[i][1] + bb0.y, 0.f); \
            v0.z = fmaxf(c[i][2] + bb0.z, 0.f); v0.w = fmaxf(c[i][3] + bb0.w, 0.f); \
            v1.x = fmaxf(c[i][4] + bb1.x, 0.f); v1.y = fmaxf(c[i][5] + bb1.y, 0.f); \
            v1.z = fmaxf(c[i][6] + bb1.z, 0.f); v1.w = fmaxf(c[i][7] + bb1.w, 0.f); \
            *(float4*)(sH + (ty * 4 + i) * H_STRIDE + tx4)      = v0;            \
            *(float4*)(sH + (ty * 4 + i) * H_STRIDE + 64 + tx4) = v1;            \
        }                                                                        \
    }

    // ---------------- Per-task loop ----------------
    for (int n = 0; n < Nt; ++n) {
        float c[4][8];

        // ===== GEMM1: state[64x256] x W1[n] -> relu -> sH =====
        {
            const float* Wn = W1 + (size_t)n * (Sn * Hn);
            // prolog: tile 0 (A slice + W slice)
            cp16(sA_u + (ar * A_STRIDE + ac) * 4,
                 state + (size_t)(row0 + ar) * Sn + ac);
            cp16(sW_u + (tid * 4) * 4,          Wn + tid * 4);
            cp16(sW_u + (1024 + tid * 4) * 4,   Wn + 1024 + tid * 4);
            cp_commit();

            #pragma unroll
            for (int i = 0; i < 4; ++i)
                #pragma unroll
                for (int j = 0; j < 8; ++j) c[i][j] = 0.f;

            for (int kt = 0; kt < 16; ++kt) {
                cp_wait0();
                __syncthreads();
                if (kt < 15) {
                    int nb = (kt + 1) & 1;
                    cp16(sA_u + (nb * 64 * A_STRIDE + ar * A_STRIDE + ac) * 4,
                         state + (size_t)(row0 + ar) * Sn + (kt + 1) * 16 + ac);
                    cp16(sW_u + (nb * 2048 + tid * 4) * 4,
                         Wn + (kt + 1) * 2048 + tid * 4);
                    cp16(sW_u + (nb * 2048 + 1024 + tid * 4) * 4,
                         Wn + (kt + 1) * 2048 + 1024 + tid * 4);
                    cp_commit();
                }
                const float* bufA = sA + (kt & 1) * 64 * A_STRIDE;
                const float* bufW = sW + (kt & 1) * 2048;
                #pragma unroll
                for (int k = 0; k < 16; ++k)
                    KSTEP(bufA, A_STRIDE, k, bufW + k * 128);
            }
            RELU_STORE_H(b1 + (size_t)n * Hn);
        }

        // ===== GEMM2: sH x W2[n] -> relu -> sH =====
        {
            const float* Wn = W2 + (size_t)n * (Hn * Hn);
            cp16(sW_u + (tid * 4) * 4,        Wn + tid * 4);
            cp16(sW_u + (1024 + tid * 4) * 4, Wn + 1024 + tid * 4);
            cp_commit();

            #pragma unroll
            for (int i = 0; i < 4; ++i)
                #pragma unroll
                for (int j = 0; j < 8; ++j) c[i][j] = 0.f;

            for (int kt = 0; kt < 8; ++kt) {
                cp_wait0();
                __syncthreads();     // also publishes sH from GEMM1 at kt=0
                if (kt < 7) {
                    int nb = (kt + 1) & 1;
                    cp16(sW_u + (nb * 2048 + tid * 4) * 4,
                         Wn + (kt + 1) * 2048 + tid * 4);
                    cp16(sW_u + (nb * 2048 + 1024 + tid * 4) * 4,
                         Wn + (kt + 1) * 2048 + 1024 + tid * 4);
                    cp_commit();
                }
                const float* bufW = sW + (kt & 1) * 2048;
                #pragma unroll
                for (int k = 0; k < 16; ++k)
                    KSTEP(sH, H_STRIDE, kt * 16 + k, bufW + k * 128);
            }
            __syncthreads();         // all sH reads done before overwrite
            RELU_STORE_H(b2 + (size_t)n * Hn);
        }

        // ===== GEMM3: sH x W3[n] -> q (+ epilogue) =====
        {
            const float* Wn = W3 + (size_t)n * (Hn * En);
            cp16(sW_u + (tid * 4) * 4,        Wn + tid * 4);
            cp16(sW_u + (1024 + tid * 4) * 4, Wn + 1024 + tid * 4);
            cp_commit();

            #pragma unroll
            for (int i = 0; i < 4; ++i)
                #pragma unroll
                for (int j = 0; j < 8; ++j) c[i][j] = 0.f;

            for (int kt = 0; kt < 8; ++kt) {
                cp_wait0();
                __syncthreads();     // publishes sH from GEMM2 at kt=0
                if (kt < 7) {
                    int nb = (kt + 1) & 1;
                    cp16(sW_u + (nb * 2048 + tid * 4) * 4,
                         Wn + (kt + 1) * 2048 + tid * 4);
                    cp16(sW_u + (nb * 2048 + 1024 + tid * 4) * 4,
                         Wn + (kt + 1) * 2048 + 1024 + tid * 4);
                    cp_commit();
                }
                const float* bufW = sW + (kt & 1) * 2048;
                #pragma unroll
                for (int k = 0; k < 16; ++k)
                    KSTEP(sH, H_STRIDE, kt * 16 + k, bufW + k * 128);
            }

            // Epilogue: bias, normalize, cos, latent accumulation
            const float* bv = b3 + (size_t)n * En;
            float4 bb0 = *(const float4*)(bv + tx4);
            float4 bb1 = *(const float4*)(bv + 64 + tx4);
            float bb[8] = {bb0.x, bb0.y, bb0.z, bb0.w, bb1.x, bb1.y, bb1.z, bb1.w};
            #pragma unroll
            for (int i = 0; i < 4; ++i) {
                #pragma unroll
                for (int j = 0; j < 8; ++j) c[i][j] += bb[j];

                float ss = 0.f;
                #pragma unroll
                for (int j = 0; j < 8; ++j) ss += c[i][j] * c[i][j];
                #pragma unroll
                for (int o = 1; o < 16; o <<= 1) ss += __shfl_xor_sync(0xffffffffu, ss, o);
                float inv = rsqrtf(ss);

                int rloc = ty * 4 + i;
                int tsk  = sTid[rloc];

                const float* lg = sLang + tsk * 128;
                float4 l0 = *(const float4*)(lg + tx4);
                float4 l1 = *(const float4*)(lg + 64 + tx4);
                float lv[8] = {l0.x, l0.y, l0.z, l0.w, l1.x, l1.y, l1.z, l1.w};

                float qh[8];
                float dot = 0.f;
                #pragma unroll
                for (int j = 0; j < 8; ++j) {
                    qh[j] = c[i][j] * inv;
                    dot += qh[j] * lv[j];
                }
                #pragma unroll
                for (int o = 1; o < 16; o <<= 1) dot += __shfl_xor_sync(0xffffffffu, dot, o);
                if (tx == 0) sCos[rloc * Nt + n] = dot;

                float p = sP[rloc * Nt + n];
                #pragma unroll
                for (int j = 0; j < 8; ++j) lat[i][j] = fmaf(qh[j], p, lat[i][j]);

                if (tsk == n) {
                    size_t base = OFF_LT + (size_t)(row0 + rloc) * En;
                    *(float4*)(out + base + tx4)      = make_float4(qh[0], qh[1], qh[2], qh[3]);
                    *(float4*)(out + base + 64 + tx4) = make_float4(qh[4], qh[5], qh[6], qh[7]);
                }
            }
        }
    }
    __syncthreads();   // sCos complete

    // ---------------- Final outputs ----------------
    if (tid < TB) {
        float m = -1e30f;
        #pragma unroll
        for (int n = 0; n < Nt; ++n) m = fmaxf(m, sCos[tid * Nt + n] * (1.0f / TEMP));
        float s = 0.f;
        #pragma unroll
        for (int n = 0; n < Nt; ++n) s += expf(sCos[tid * Nt + n] * (1.0f / TEMP) - m);
        float lse = m + logf(s);
        float* o = out + OFF_LOGP + (size_t)(row0 + tid) * Nt;
        #pragma unroll
        for (int n = 0; n < Nt; ++n) o[n] = sCos[tid * Nt + n] * (1.0f / TEMP) - lse;
    }

    #pragma unroll
    for (int i = 0; i < 4; ++i) {
        int r = row0 + ty * 4 + i;
        float4 v0 = make_float4(lat[i][0], lat[i][1], lat[i][2], lat[i][3]);
        float4 v1 = make_float4(lat[i][4], lat[i][5], lat[i][6], lat[i][7]);
        *(float4*)(out + (size_t)r * (Sn + En) + Sn + tx4)      = v0;
        *(float4*)(out + (size_t)r * (Sn + En) + Sn + 64 + tx4) = v1;
        *(float4*)(out + OFF_LV + (size_t)r * En + tx4)         = v0;
        *(float4*)(out + OFF_LV + (size_t)r * En + 64 + tx4)    = v1;
    }

    // rep_vec[:,0:256] = state (stream from L2)
    for (int idx = tid; idx < TB * (Sn / 4); idx += THREADS) {
        int r  = idx >> 6;           // Sn/4 = 64 float4 per row
        int c4 = idx & 63;
        float4 v = ((const float4*)(state + (size_t)(row0 + r) * Sn))[c4];
        *(float4*)(out + (size_t)(row0 + r) * (Sn + En) + c4 * 4) = v;
    }
}

extern "C" void kernel_launch(void* const* d_in, const int* in_sizes, int n_in,
                              void* d_out, int out_size) {
    const float* state    = (const float*)d_in[0];
    const int*   task_id  = (const int*)  d_in[1];
    const float* prior    = (const float*)d_in[2];
    const float* W1       = (const float*)d_in[3];
    const float* b1       = (const float*)d_in[4];
    const float* W2       = (const float*)d_in[5];
    const float* b2       = (const float*)d_in[6];
    const float* W3       = (const float*)d_in[7];
    const float* b3       = (const float*)d_in[8];
    const float* lang_emb = (const float*)d_in[9];
    float* out = (float*)d_out;

    size_t smem = (size_t)SMEM_WORDS * sizeof(float);

    static bool attr_set = false;
    if (!attr_set) {
        cudaFuncSetAttribute(slp_encoder_fused,
                             cudaFuncAttributeMaxDynamicSharedMemorySize,
                             (int)smem);
        attr_set = true;
    }

    slp_encoder_fused<<<Bn / TB, THREADS, smem>>>(
        state, task_id, prior, W1, b1, W2, b2, W3, b3, lang_emb, out);
}